// round 9
// baseline (speedup 1.0000x reference)
#include <cuda_runtime.h>
#include <cstdint>

#define N_NODES 10000
#define N_EDGES 320000
#define F 128
#define NCLS 64

// Node-level tables (L2-resident) + CSR scratch.
__device__ __align__(16) float g_N1[N_NODES * F];   // aggregated node features (pre-scaled by invdeg)
__device__ __align__(16) float g_Y[N_NODES * F];    // node GEMM output
__device__ float g_invdeg[N_NODES];
__device__ int   g_cnt[N_NODES];
__device__ int   g_rowptr[N_NODES];
__device__ int   g_cursor[N_NODES];
__device__ __align__(8) int2 g_pair[N_EDGES];  // (src node id, original edge id), grouped by dst

__global__ void k_zero_cnt() {
    int i = blockIdx.x * blockDim.x + threadIdx.x;
    if (i < N_NODES) g_cnt[i] = 0;
}

__global__ void k_hist(const int* __restrict__ dst) {
    int e = blockIdx.x * blockDim.x + threadIdx.x;
    if (e < N_EDGES) atomicAdd(&g_cnt[dst[e]], 1);
}

// Single-block exclusive scan over 10000 counts -> rowptr, cursor, invdeg.
__global__ void k_scan() {
    __shared__ int warp_sums[32];
    const int CH = 10;                       // 1024 * 10 >= 10000
    int tid = threadIdx.x;
    int base = tid * CH;
    int local[CH];
    int s = 0;
#pragma unroll
    for (int i = 0; i < CH; i++) {
        int idx = base + i;
        int v = (idx < N_NODES) ? g_cnt[idx] : 0;
        local[i] = s;
        s += v;
    }
    int lane = tid & 31, wid = tid >> 5;
    int x = s;
#pragma unroll
    for (int off = 1; off < 32; off <<= 1) {
        int y = __shfl_up_sync(0xffffffffu, x, off);
        if (lane >= off) x += y;
    }
    if (lane == 31) warp_sums[wid] = x;
    __syncthreads();
    if (wid == 0) {
        int y = warp_sums[lane];
#pragma unroll
        for (int off = 1; off < 32; off <<= 1) {
            int z = __shfl_up_sync(0xffffffffu, y, off);
            if (lane >= off) y += z;
        }
        warp_sums[lane] = y;
    }
    __syncthreads();
    int thread_excl = x - s + ((wid > 0) ? warp_sums[wid - 1] : 0);
#pragma unroll
    for (int i = 0; i < CH; i++) {
        int idx = base + i;
        if (idx < N_NODES) {
            int rp = thread_excl + local[i];
            g_rowptr[idx] = rp;
            g_cursor[idx] = rp;
            g_invdeg[idx] = 1.0f / (float)g_cnt[idx];
        }
    }
}

__global__ void k_fill(const int* __restrict__ src, const int* __restrict__ dst) {
    int e = blockIdx.x * blockDim.x + threadIdx.x;
    if (e >= N_EDGES) return;
    int d = dst[e];
    int pos = atomicAdd(&g_cursor[d], 1);
    g_pair[pos] = make_int2(src[e], e);
}

// Layer-1 aggregation: N1[d] = invdeg[d] * sum_{in-edges} ef[e].  Warp per node.
__global__ void k_aggr_feats(const float* __restrict__ ef) {
    int node = blockIdx.x * (blockDim.x >> 5) + (threadIdx.x >> 5);
    if (node >= N_NODES) return;
    int lane = threadIdx.x & 31;
    int rp = g_rowptr[node], deg = g_cnt[node];
    float4 a0 = make_float4(0.f, 0.f, 0.f, 0.f);
    float4 a1 = make_float4(0.f, 0.f, 0.f, 0.f);
    for (int base = 0; base < deg; base += 32) {
        int rem = deg - base;
        int cnt = rem < 32 ? rem : 32;
        int eid = (lane < cnt) ? g_pair[rp + base + lane].y : 0;
        int j = 0;
        for (; j + 4 <= cnt; j += 4) {
            int e0 = __shfl_sync(0xffffffffu, eid, j + 0);
            int e1 = __shfl_sync(0xffffffffu, eid, j + 1);
            int e2 = __shfl_sync(0xffffffffu, eid, j + 2);
            int e3 = __shfl_sync(0xffffffffu, eid, j + 3);
            float4 v0 = reinterpret_cast<const float4*>(ef + (size_t)e0 * F)[lane];
            float4 v1 = reinterpret_cast<const float4*>(ef + (size_t)e1 * F)[lane];
            float4 v2 = reinterpret_cast<const float4*>(ef + (size_t)e2 * F)[lane];
            float4 v3 = reinterpret_cast<const float4*>(ef + (size_t)e3 * F)[lane];
            a0.x += v0.x + v1.x; a0.y += v0.y + v1.y; a0.z += v0.z + v1.z; a0.w += v0.w + v1.w;
            a1.x += v2.x + v3.x; a1.y += v2.y + v3.y; a1.z += v2.z + v3.z; a1.w += v2.w + v3.w;
        }
        for (; j < cnt; j++) {
            int e = __shfl_sync(0xffffffffu, eid, j);
            float4 v = reinterpret_cast<const float4*>(ef + (size_t)e * F)[lane];
            a0.x += v.x; a0.y += v.y; a0.z += v.z; a0.w += v.w;
        }
    }
    float inv = g_invdeg[node];
    float4 acc;
    acc.x = (a0.x + a1.x) * inv; acc.y = (a0.y + a1.y) * inv;
    acc.z = (a0.z + a1.z) * inv; acc.w = (a0.w + a1.w) * inv;
    reinterpret_cast<float4*>(g_N1 + (size_t)node * F)[lane] = acc;
}

// Fused send/recv + node GEMM.
// Block = 256 threads handles 8 nodes. Phase 1: warp w gathers node (blk*8+w)'s
// aggregate sum_{in-edges} N1[src] into shared As[w]. Phase 2: GEMM
// Y[node][col] = dot(As[node], W[col]) with 256 threads (256/FOUT groups of rows).
template<int FOUT>
__global__ void k_sr_gemm(const float* __restrict__ W) {
    __shared__ __align__(16) float As[8 * F];
    int tid = threadIdx.x;
    int wid = tid >> 5, lane = tid & 31;
    int node0 = blockIdx.x * 8;
    int node = node0 + wid;

    // ---- gather phase (warp per node) ----
    {
        int rp = g_rowptr[node], deg = g_cnt[node];
        float4 a0 = make_float4(0.f, 0.f, 0.f, 0.f);
        float4 a1 = make_float4(0.f, 0.f, 0.f, 0.f);
        for (int base = 0; base < deg; base += 32) {
            int rem = deg - base;
            int cnt = rem < 32 ? rem : 32;
            int sreg = (lane < cnt) ? g_pair[rp + base + lane].x : 0;
            int j = 0;
            for (; j + 4 <= cnt; j += 4) {
                int s0 = __shfl_sync(0xffffffffu, sreg, j + 0);
                int s1 = __shfl_sync(0xffffffffu, sreg, j + 1);
                int s2 = __shfl_sync(0xffffffffu, sreg, j + 2);
                int s3 = __shfl_sync(0xffffffffu, sreg, j + 3);
                float4 v0 = reinterpret_cast<const float4*>(g_N1 + (size_t)s0 * F)[lane];
                float4 v1 = reinterpret_cast<const float4*>(g_N1 + (size_t)s1 * F)[lane];
                float4 v2 = reinterpret_cast<const float4*>(g_N1 + (size_t)s2 * F)[lane];
                float4 v3 = reinterpret_cast<const float4*>(g_N1 + (size_t)s3 * F)[lane];
                a0.x += v0.x + v1.x; a0.y += v0.y + v1.y; a0.z += v0.z + v1.z; a0.w += v0.w + v1.w;
                a1.x += v2.x + v3.x; a1.y += v2.y + v3.y; a1.z += v2.z + v3.z; a1.w += v2.w + v3.w;
            }
            for (; j < cnt; j++) {
                int s = __shfl_sync(0xffffffffu, sreg, j);
                float4 v = reinterpret_cast<const float4*>(g_N1 + (size_t)s * F)[lane];
                a0.x += v.x; a0.y += v.y; a0.z += v.z; a0.w += v.w;
            }
        }
        float4 acc;
        acc.x = a0.x + a1.x; acc.y = a0.y + a1.y; acc.z = a0.z + a1.z; acc.w = a0.w + a1.w;
        reinterpret_cast<float4*>(As + wid * F)[lane] = acc;
    }
    __syncthreads();

    // ---- GEMM phase ----
    const int NGRP = 256 / FOUT;     // groups of columns
    const int RPG = 8 / NGRP;        // rows per group
    int col = tid % FOUT;
    int grp = tid / FOUT;

    float acc[RPG];
#pragma unroll
    for (int r = 0; r < RPG; r++) acc[r] = 0.0f;

    const float4* W4 = reinterpret_cast<const float4*>(W + (size_t)col * F);
#pragma unroll 4
    for (int k4 = 0; k4 < F / 4; k4++) {
        float4 w = W4[k4];
#pragma unroll
        for (int r = 0; r < RPG; r++) {
            float4 a = reinterpret_cast<const float4*>(As + (grp * RPG + r) * F)[k4];
            acc[r] += a.x * w.x + a.y * w.y + a.z * w.z + a.w * w.w;
        }
    }
#pragma unroll
    for (int r = 0; r < RPG; r++)
        g_Y[(size_t)(node0 + grp * RPG + r) * FOUT + col] = acc[r];
}

// Edge update fused with next layer's aggregation:
// N1[d] = invdeg[d] * sum_{in-edges e} relu((Y[src_e]+Y[d])*0.5 + b).  Warp per node.
__global__ void k_edge_update(const float* __restrict__ b) {
    int node = blockIdx.x * (blockDim.x >> 5) + (threadIdx.x >> 5);
    if (node >= N_NODES) return;
    int lane = threadIdx.x & 31;
    int rp = g_rowptr[node], deg = g_cnt[node];
    float4 yd = reinterpret_cast<const float4*>(g_Y + (size_t)node * F)[lane];
    float4 bb = reinterpret_cast<const float4*>(b)[lane];
    // fold: relu((ys+yd)*0.5 + b) = relu(ys*0.5 + (yd*0.5+b))
    float4 c;
    c.x = yd.x * 0.5f + bb.x; c.y = yd.y * 0.5f + bb.y;
    c.z = yd.z * 0.5f + bb.z; c.w = yd.w * 0.5f + bb.w;
    float4 a0 = make_float4(0.f, 0.f, 0.f, 0.f);
    float4 a1 = make_float4(0.f, 0.f, 0.f, 0.f);
    for (int base = 0; base < deg; base += 32) {
        int rem = deg - base;
        int cnt = rem < 32 ? rem : 32;
        int sreg = (lane < cnt) ? g_pair[rp + base + lane].x : 0;
        int j = 0;
        for (; j + 4 <= cnt; j += 4) {
            int s0 = __shfl_sync(0xffffffffu, sreg, j + 0);
            int s1 = __shfl_sync(0xffffffffu, sreg, j + 1);
            int s2 = __shfl_sync(0xffffffffu, sreg, j + 2);
            int s3 = __shfl_sync(0xffffffffu, sreg, j + 3);
            float4 v0 = reinterpret_cast<const float4*>(g_Y + (size_t)s0 * F)[lane];
            float4 v1 = reinterpret_cast<const float4*>(g_Y + (size_t)s1 * F)[lane];
            float4 v2 = reinterpret_cast<const float4*>(g_Y + (size_t)s2 * F)[lane];
            float4 v3 = reinterpret_cast<const float4*>(g_Y + (size_t)s3 * F)[lane];
            a0.x += fmaxf(0.0f, v0.x * 0.5f + c.x) + fmaxf(0.0f, v1.x * 0.5f + c.x);
            a0.y += fmaxf(0.0f, v0.y * 0.5f + c.y) + fmaxf(0.0f, v1.y * 0.5f + c.y);
            a0.z += fmaxf(0.0f, v0.z * 0.5f + c.z) + fmaxf(0.0f, v1.z * 0.5f + c.z);
            a0.w += fmaxf(0.0f, v0.w * 0.5f + c.w) + fmaxf(0.0f, v1.w * 0.5f + c.w);
            a1.x += fmaxf(0.0f, v2.x * 0.5f + c.x) + fmaxf(0.0f, v3.x * 0.5f + c.x);
            a1.y += fmaxf(0.0f, v2.y * 0.5f + c.y) + fmaxf(0.0f, v3.y * 0.5f + c.y);
            a1.z += fmaxf(0.0f, v2.z * 0.5f + c.z) + fmaxf(0.0f, v3.z * 0.5f + c.z);
            a1.w += fmaxf(0.0f, v2.w * 0.5f + c.w) + fmaxf(0.0f, v3.w * 0.5f + c.w);
        }
        for (; j < cnt; j++) {
            int s = __shfl_sync(0xffffffffu, sreg, j);
            float4 v = reinterpret_cast<const float4*>(g_Y + (size_t)s * F)[lane];
            a0.x += fmaxf(0.0f, v.x * 0.5f + c.x);
            a0.y += fmaxf(0.0f, v.y * 0.5f + c.y);
            a0.z += fmaxf(0.0f, v.z * 0.5f + c.z);
            a0.w += fmaxf(0.0f, v.w * 0.5f + c.w);
        }
    }
    float inv = g_invdeg[node];
    float4 acc;
    acc.x = (a0.x + a1.x) * inv; acc.y = (a0.y + a1.y) * inv;
    acc.z = (a0.z + a1.z) * inv; acc.w = (a0.w + a1.w) * inv;
    reinterpret_cast<float4*>(g_N1 + (size_t)node * F)[lane] = acc;
}

// Final layer (FOUT=64, no relu): out[e] = (Y[src]+Y[dst])*0.5 + b5, original edge order.
__global__ void k_final(const int* __restrict__ src, const int* __restrict__ dst,
                        const float* __restrict__ b, float* __restrict__ out) {
    int warp = blockIdx.x * (blockDim.x >> 5) + (threadIdx.x >> 5);
    int lane = threadIdx.x & 31;
    int e = warp * 2 + (lane >> 4);
    if (e >= N_EDGES) return;
    int l16 = lane & 15;
    int s = src[e], d = dst[e];
    float4 ys = reinterpret_cast<const float4*>(g_Y + (size_t)s * NCLS)[l16];
    float4 yd = reinterpret_cast<const float4*>(g_Y + (size_t)d * NCLS)[l16];
    float4 bb = reinterpret_cast<const float4*>(b)[l16];
    float4 v;
    v.x = (ys.x + yd.x) * 0.5f + bb.x;
    v.y = (ys.y + yd.y) * 0.5f + bb.y;
    v.z = (ys.z + yd.z) * 0.5f + bb.z;
    v.w = (ys.w + yd.w) * 0.5f + bb.w;
    reinterpret_cast<float4*>(out)[(size_t)e * (NCLS / 4) + l16] = v;
}

extern "C" void kernel_launch(void* const* d_in, const int* in_sizes, int n_in,
                              void* d_out, int out_size) {
    const float* ef  = (const float*)d_in[0];
    const int*   src = (const int*)d_in[1];
    const int*   dst = (const int*)d_in[2];
    const float* W1 = (const float*)d_in[3];  const float* b1 = (const float*)d_in[4];
    const float* W2 = (const float*)d_in[5];  const float* b2 = (const float*)d_in[6];
    const float* W3 = (const float*)d_in[7];  const float* b3 = (const float*)d_in[8];
    const float* W4 = (const float*)d_in[9];  const float* b4 = (const float*)d_in[10];
    const float* W5 = (const float*)d_in[11]; const float* b5 = (const float*)d_in[12];
    float* out = (float*)d_out;

    const int NB = (N_NODES + 7) / 8;   // warp-per-node blocks (256 thr = 8 warps)

    // CSR build (counting sort by dst)
    k_zero_cnt<<<(N_NODES + 255) / 256, 256>>>();
    k_hist<<<N_EDGES / 256, 256>>>(dst);
    k_scan<<<1, 1024>>>();
    k_fill<<<N_EDGES / 256, 256>>>(src, dst);

    // layer-1 input aggregation
    k_aggr_feats<<<NB, 256>>>(ef);

    const float* Ws[4] = {W1, W2, W3, W4};
    const float* bs[4] = {b1, b2, b3, b4};
    for (int l = 0; l < 4; l++) {
        k_sr_gemm<F><<<N_NODES / 8, 256>>>(Ws[l]);       // gather + GEMM fused
        k_edge_update<<<NB, 256>>>(bs[l]);               // N1[d] = invdeg*sum relu(...)
    }

    // final layer
    k_sr_gemm<NCLS><<<N_NODES / 8, 256>>>(W5);
    k_final<<<N_EDGES / 16, 256>>>(src, dst, b5, out);
}

// round 10
// speedup vs baseline: 1.3403x; 1.3403x over previous
#include <cuda_runtime.h>
#include <cstdint>

#define N_NODES 10000
#define N_EDGES 320000
#define F 128
#define NCLS 64

// Node-level tables (L2-resident) + CSR scratch.
__device__ __align__(16) float g_N1[N_NODES * F];   // aggregated node features (pre-scaled by invdeg)
__device__ __align__(16) float g_N2[N_NODES * F];   // send/recv result
__device__ __align__(16) float g_Y[N_NODES * F];    // node GEMM output
__device__ float g_invdeg[N_NODES];
__device__ int   g_cnt[N_NODES];
__device__ int   g_rowptr[N_NODES];
__device__ int   g_cursor[N_NODES];
__device__ __align__(8) int2 g_pair[N_EDGES];  // (src node id, original edge id), grouped by dst

__global__ void k_zero_cnt() {
    int i = blockIdx.x * blockDim.x + threadIdx.x;
    if (i < N_NODES) g_cnt[i] = 0;
}

__global__ void k_hist(const int* __restrict__ dst) {
    int e = blockIdx.x * blockDim.x + threadIdx.x;
    if (e < N_EDGES) atomicAdd(&g_cnt[dst[e]], 1);
}

// Single-block exclusive scan over 10000 counts -> rowptr, cursor, invdeg.
__global__ void k_scan() {
    __shared__ int warp_sums[32];
    const int CH = 10;                       // 1024 * 10 >= 10000
    int tid = threadIdx.x;
    int base = tid * CH;
    int local[CH];
    int s = 0;
#pragma unroll
    for (int i = 0; i < CH; i++) {
        int idx = base + i;
        int v = (idx < N_NODES) ? g_cnt[idx] : 0;
        local[i] = s;
        s += v;
    }
    int lane = tid & 31, wid = tid >> 5;
    int x = s;
#pragma unroll
    for (int off = 1; off < 32; off <<= 1) {
        int y = __shfl_up_sync(0xffffffffu, x, off);
        if (lane >= off) x += y;
    }
    if (lane == 31) warp_sums[wid] = x;
    __syncthreads();
    if (wid == 0) {
        int y = warp_sums[lane];
#pragma unroll
        for (int off = 1; off < 32; off <<= 1) {
            int z = __shfl_up_sync(0xffffffffu, y, off);
            if (lane >= off) y += z;
        }
        warp_sums[lane] = y;
    }
    __syncthreads();
    int thread_excl = x - s + ((wid > 0) ? warp_sums[wid - 1] : 0);
#pragma unroll
    for (int i = 0; i < CH; i++) {
        int idx = base + i;
        if (idx < N_NODES) {
            int rp = thread_excl + local[i];
            g_rowptr[idx] = rp;
            g_cursor[idx] = rp;
            g_invdeg[idx] = 1.0f / (float)g_cnt[idx];
        }
    }
}

__global__ void k_fill(const int* __restrict__ src, const int* __restrict__ dst) {
    int e = blockIdx.x * blockDim.x + threadIdx.x;
    if (e >= N_EDGES) return;
    int d = dst[e];
    int pos = atomicAdd(&g_cursor[d], 1);
    g_pair[pos] = make_int2(src[e], e);
}

// Layer-1 aggregation: N1[d] = invdeg[d] * sum_{in-edges} ef[e].  Warp per node.
__global__ void k_aggr_feats(const float* __restrict__ ef) {
    int node = blockIdx.x * (blockDim.x >> 5) + (threadIdx.x >> 5);
    if (node >= N_NODES) return;
    int lane = threadIdx.x & 31;
    int rp = g_rowptr[node], deg = g_cnt[node];
    float4 a0 = make_float4(0.f, 0.f, 0.f, 0.f);
    float4 a1 = make_float4(0.f, 0.f, 0.f, 0.f);
    for (int base = 0; base < deg; base += 32) {
        int rem = deg - base;
        int cnt = rem < 32 ? rem : 32;
        int eid = (lane < cnt) ? g_pair[rp + base + lane].y : 0;
        int j = 0;
        for (; j + 4 <= cnt; j += 4) {
            int e0 = __shfl_sync(0xffffffffu, eid, j + 0);
            int e1 = __shfl_sync(0xffffffffu, eid, j + 1);
            int e2 = __shfl_sync(0xffffffffu, eid, j + 2);
            int e3 = __shfl_sync(0xffffffffu, eid, j + 3);
            float4 v0 = reinterpret_cast<const float4*>(ef + (size_t)e0 * F)[lane];
            float4 v1 = reinterpret_cast<const float4*>(ef + (size_t)e1 * F)[lane];
            float4 v2 = reinterpret_cast<const float4*>(ef + (size_t)e2 * F)[lane];
            float4 v3 = reinterpret_cast<const float4*>(ef + (size_t)e3 * F)[lane];
            a0.x += v0.x + v1.x; a0.y += v0.y + v1.y; a0.z += v0.z + v1.z; a0.w += v0.w + v1.w;
            a1.x += v2.x + v3.x; a1.y += v2.y + v3.y; a1.z += v2.z + v3.z; a1.w += v2.w + v3.w;
        }
        for (; j < cnt; j++) {
            int e = __shfl_sync(0xffffffffu, eid, j);
            float4 v = reinterpret_cast<const float4*>(ef + (size_t)e * F)[lane];
            a0.x += v.x; a0.y += v.y; a0.z += v.z; a0.w += v.w;
        }
    }
    float inv = g_invdeg[node];
    float4 acc;
    acc.x = (a0.x + a1.x) * inv; acc.y = (a0.y + a1.y) * inv;
    acc.z = (a0.z + a1.z) * inv; acc.w = (a0.w + a1.w) * inv;
    reinterpret_cast<float4*>(g_N1 + (size_t)node * F)[lane] = acc;
}

// Send/recv: N2[d] = sum_{in-edges} N1[src]   (N1 already pre-scaled by invdeg[src]).
__global__ void k_sendrecv() {
    int node = blockIdx.x * (blockDim.x >> 5) + (threadIdx.x >> 5);
    if (node >= N_NODES) return;
    int lane = threadIdx.x & 31;
    int rp = g_rowptr[node], deg = g_cnt[node];
    float4 a0 = make_float4(0.f, 0.f, 0.f, 0.f);
    float4 a1 = make_float4(0.f, 0.f, 0.f, 0.f);
    for (int base = 0; base < deg; base += 32) {
        int rem = deg - base;
        int cnt = rem < 32 ? rem : 32;
        int sreg = (lane < cnt) ? g_pair[rp + base + lane].x : 0;
        int j = 0;
        for (; j + 4 <= cnt; j += 4) {
            int s0 = __shfl_sync(0xffffffffu, sreg, j + 0);
            int s1 = __shfl_sync(0xffffffffu, sreg, j + 1);
            int s2 = __shfl_sync(0xffffffffu, sreg, j + 2);
            int s3 = __shfl_sync(0xffffffffu, sreg, j + 3);
            float4 v0 = reinterpret_cast<const float4*>(g_N1 + (size_t)s0 * F)[lane];
            float4 v1 = reinterpret_cast<const float4*>(g_N1 + (size_t)s1 * F)[lane];
            float4 v2 = reinterpret_cast<const float4*>(g_N1 + (size_t)s2 * F)[lane];
            float4 v3 = reinterpret_cast<const float4*>(g_N1 + (size_t)s3 * F)[lane];
            a0.x += v0.x + v1.x; a0.y += v0.y + v1.y; a0.z += v0.z + v1.z; a0.w += v0.w + v1.w;
            a1.x += v2.x + v3.x; a1.y += v2.y + v3.y; a1.z += v2.z + v3.z; a1.w += v2.w + v3.w;
        }
        for (; j < cnt; j++) {
            int s = __shfl_sync(0xffffffffu, sreg, j);
            float4 v = reinterpret_cast<const float4*>(g_N1 + (size_t)s * F)[lane];
            a0.x += v.x; a0.y += v.y; a0.z += v.z; a0.w += v.w;
        }
    }
    float4 acc;
    acc.x = a0.x + a1.x; acc.y = a0.y + a1.y; acc.z = a0.z + a1.z; acc.w = a0.w + a1.w;
    reinterpret_cast<float4*>(g_N2 + (size_t)node * F)[lane] = acc;
}

// Node GEMM: Y[n][j] = dot(N2[n], W[j]).  W is [FOUT, F] row-major.
template<int FOUT>
__global__ void k_gemm(const float* __restrict__ W) {
    __shared__ __align__(16) float As[16 * F];
    int tid = threadIdx.x;
    int r0 = blockIdx.x * 16;

    const float4* A4 = reinterpret_cast<const float4*>(g_N2 + (size_t)r0 * F);
    float4* S4 = reinterpret_cast<float4*>(As);
    for (int i = tid; i < 16 * F / 4; i += FOUT) S4[i] = A4[i];
    __syncthreads();

    float acc[16];
#pragma unroll
    for (int r = 0; r < 16; r++) acc[r] = 0.0f;

    const float4* W4 = reinterpret_cast<const float4*>(W + (size_t)tid * F);
#pragma unroll 4
    for (int k4 = 0; k4 < F / 4; k4++) {
        float4 w = W4[k4];
#pragma unroll
        for (int r = 0; r < 16; r++) {
            float4 a = reinterpret_cast<const float4*>(As + r * F)[k4];
            acc[r] += a.x * w.x + a.y * w.y + a.z * w.z + a.w * w.w;
        }
    }
#pragma unroll
    for (int r = 0; r < 16; r++)
        g_Y[(size_t)(r0 + r) * FOUT + tid] = acc[r];
}

// Edge update fused with next layer's aggregation:
// N1[d] = invdeg[d] * sum_{in-edges e} relu((Y[src_e]+Y[d])*0.5 + b).  Warp per node.
__global__ void k_edge_update(const float* __restrict__ b) {
    int node = blockIdx.x * (blockDim.x >> 5) + (threadIdx.x >> 5);
    if (node >= N_NODES) return;
    int lane = threadIdx.x & 31;
    int rp = g_rowptr[node], deg = g_cnt[node];
    float4 yd = reinterpret_cast<const float4*>(g_Y + (size_t)node * F)[lane];
    float4 bb = reinterpret_cast<const float4*>(b)[lane];
    // fold: relu((ys+yd)*0.5 + b) = relu(ys*0.5 + (yd*0.5+b))
    float4 c;
    c.x = yd.x * 0.5f + bb.x; c.y = yd.y * 0.5f + bb.y;
    c.z = yd.z * 0.5f + bb.z; c.w = yd.w * 0.5f + bb.w;
    float4 a0 = make_float4(0.f, 0.f, 0.f, 0.f);
    float4 a1 = make_float4(0.f, 0.f, 0.f, 0.f);
    for (int base = 0; base < deg; base += 32) {
        int rem = deg - base;
        int cnt = rem < 32 ? rem : 32;
        int sreg = (lane < cnt) ? g_pair[rp + base + lane].x : 0;
        int j = 0;
        for (; j + 4 <= cnt; j += 4) {
            int s0 = __shfl_sync(0xffffffffu, sreg, j + 0);
            int s1 = __shfl_sync(0xffffffffu, sreg, j + 1);
            int s2 = __shfl_sync(0xffffffffu, sreg, j + 2);
            int s3 = __shfl_sync(0xffffffffu, sreg, j + 3);
            float4 v0 = reinterpret_cast<const float4*>(g_Y + (size_t)s0 * F)[lane];
            float4 v1 = reinterpret_cast<const float4*>(g_Y + (size_t)s1 * F)[lane];
            float4 v2 = reinterpret_cast<const float4*>(g_Y + (size_t)s2 * F)[lane];
            float4 v3 = reinterpret_cast<const float4*>(g_Y + (size_t)s3 * F)[lane];
            a0.x += fmaxf(0.0f, v0.x * 0.5f + c.x) + fmaxf(0.0f, v1.x * 0.5f + c.x);
            a0.y += fmaxf(0.0f, v0.y * 0.5f + c.y) + fmaxf(0.0f, v1.y * 0.5f + c.y);
            a0.z += fmaxf(0.0f, v0.z * 0.5f + c.z) + fmaxf(0.0f, v1.z * 0.5f + c.z);
            a0.w += fmaxf(0.0f, v0.w * 0.5f + c.w) + fmaxf(0.0f, v1.w * 0.5f + c.w);
            a1.x += fmaxf(0.0f, v2.x * 0.5f + c.x) + fmaxf(0.0f, v3.x * 0.5f + c.x);
            a1.y += fmaxf(0.0f, v2.y * 0.5f + c.y) + fmaxf(0.0f, v3.y * 0.5f + c.y);
            a1.z += fmaxf(0.0f, v2.z * 0.5f + c.z) + fmaxf(0.0f, v3.z * 0.5f + c.z);
            a1.w += fmaxf(0.0f, v2.w * 0.5f + c.w) + fmaxf(0.0f, v3.w * 0.5f + c.w);
        }
        for (; j < cnt; j++) {
            int s = __shfl_sync(0xffffffffu, sreg, j);
            float4 v = reinterpret_cast<const float4*>(g_Y + (size_t)s * F)[lane];
            a0.x += fmaxf(0.0f, v.x * 0.5f + c.x);
            a0.y += fmaxf(0.0f, v.y * 0.5f + c.y);
            a0.z += fmaxf(0.0f, v.z * 0.5f + c.z);
            a0.w += fmaxf(0.0f, v.w * 0.5f + c.w);
        }
    }
    float inv = g_invdeg[node];
    float4 acc;
    acc.x = (a0.x + a1.x) * inv; acc.y = (a0.y + a1.y) * inv;
    acc.z = (a0.z + a1.z) * inv; acc.w = (a0.w + a1.w) * inv;
    reinterpret_cast<float4*>(g_N1 + (size_t)node * F)[lane] = acc;
}

// Final layer (FOUT=64, no relu), CSR order: warp per node, Y[dst] loaded once.
// out[eid] = (Y[src] + Y[dst])*0.5 + b5, written at original edge position.
__global__ void k_final_csr(const float* __restrict__ b, float* __restrict__ out) {
    int node = blockIdx.x * (blockDim.x >> 5) + (threadIdx.x >> 5);
    if (node >= N_NODES) return;
    int lane = threadIdx.x & 31;
    int rp = g_rowptr[node], deg = g_cnt[node];
    // yd and bias held in registers: lane covers floats [2*lane, 2*lane+1]
    float2 yd = reinterpret_cast<const float2*>(g_Y + (size_t)node * NCLS)[lane];
    float2 bb = reinterpret_cast<const float2*>(b)[lane];
    float2 c;  // (yd*0.5 + b)
    c.x = yd.x * 0.5f + bb.x;
    c.y = yd.y * 0.5f + bb.y;
    for (int base = 0; base < deg; base += 32) {
        int rem = deg - base;
        int cnt = rem < 32 ? rem : 32;
        int2 pr = (lane < cnt) ? g_pair[rp + base + lane] : make_int2(0, 0);
        int j = 0;
        for (; j + 2 <= cnt; j += 2) {
            int s0 = __shfl_sync(0xffffffffu, pr.x, j + 0);
            int e0 = __shfl_sync(0xffffffffu, pr.y, j + 0);
            int s1 = __shfl_sync(0xffffffffu, pr.x, j + 1);
            int e1 = __shfl_sync(0xffffffffu, pr.y, j + 1);
            float2 v0 = reinterpret_cast<const float2*>(g_Y + (size_t)s0 * NCLS)[lane];
            float2 v1 = reinterpret_cast<const float2*>(g_Y + (size_t)s1 * NCLS)[lane];
            float2 o0, o1;
            o0.x = v0.x * 0.5f + c.x; o0.y = v0.y * 0.5f + c.y;
            o1.x = v1.x * 0.5f + c.x; o1.y = v1.y * 0.5f + c.y;
            reinterpret_cast<float2*>(out)[(size_t)e0 * (NCLS / 2) + lane] = o0;
            reinterpret_cast<float2*>(out)[(size_t)e1 * (NCLS / 2) + lane] = o1;
        }
        for (; j < cnt; j++) {
            int s = __shfl_sync(0xffffffffu, pr.x, j);
            int e = __shfl_sync(0xffffffffu, pr.y, j);
            float2 v = reinterpret_cast<const float2*>(g_Y + (size_t)s * NCLS)[lane];
            float2 o;
            o.x = v.x * 0.5f + c.x; o.y = v.y * 0.5f + c.y;
            reinterpret_cast<float2*>(out)[(size_t)e * (NCLS / 2) + lane] = o;
        }
    }
}

extern "C" void kernel_launch(void* const* d_in, const int* in_sizes, int n_in,
                              void* d_out, int out_size) {
    const float* ef  = (const float*)d_in[0];
    const int*   src = (const int*)d_in[1];
    const int*   dst = (const int*)d_in[2];
    const float* W1 = (const float*)d_in[3];  const float* b1 = (const float*)d_in[4];
    const float* W2 = (const float*)d_in[5];  const float* b2 = (const float*)d_in[6];
    const float* W3 = (const float*)d_in[7];  const float* b3 = (const float*)d_in[8];
    const float* W4 = (const float*)d_in[9];  const float* b4 = (const float*)d_in[10];
    const float* W5 = (const float*)d_in[11]; const float* b5 = (const float*)d_in[12];
    float* out = (float*)d_out;

    const int NB = (N_NODES + 7) / 8;   // warp-per-node blocks (256 thr = 8 warps)

    // CSR build (counting sort by dst)
    k_zero_cnt<<<(N_NODES + 255) / 256, 256>>>();
    k_hist<<<N_EDGES / 256, 256>>>(dst);
    k_scan<<<1, 1024>>>();
    k_fill<<<N_EDGES / 256, 256>>>(src, dst);

    // layer-1 input aggregation
    k_aggr_feats<<<NB, 256>>>(ef);

    const float* Ws[4] = {W1, W2, W3, W4};
    const float* bs[4] = {b1, b2, b3, b4};
    for (int l = 0; l < 4; l++) {
        k_sendrecv<<<NB, 256>>>();                       // N2[d] = sum N1[src]
        k_gemm<F><<<N_NODES / 16, F>>>(Ws[l]);           // Y = N2 @ W^T
        k_edge_update<<<NB, 256>>>(bs[l]);               // N1[d] = invdeg*sum relu(...)
    }

    // final layer
    k_sendrecv<<<NB, 256>>>();
    k_gemm<NCLS><<<N_NODES / 16, NCLS>>>(W5);
    k_final_csr<<<NB, 256>>>(b5, out);
}

// round 12
// speedup vs baseline: 1.3805x; 1.0300x over previous
#include <cuda_runtime.h>
#include <cuda_fp16.h>
#include <cstdint>

#define N_NODES 10000
#define N_EDGES 320000
#define F 128
#define NCLS 64

// Node-level tables (L2-resident) + CSR scratch.
// Gathered tables in fp16 (halve L2 gather bytes); N2 / final Y in fp32.
__device__ __align__(16) __half g_N1h[N_NODES * F];  // aggregated node feats (invdeg-prescaled), fp16
__device__ __align__(16) float  g_N2[N_NODES * F];   // send/recv result, fp32
__device__ __align__(16) __half g_Yh[N_NODES * F];   // intermediate node GEMM output, fp16
__device__ __align__(16) float  g_Yf[N_NODES * NCLS]; // final-layer node GEMM output, fp32
__device__ float g_invdeg[N_NODES];
__device__ int   g_cnt[N_NODES];
__device__ int   g_rowptr[N_NODES];
__device__ int   g_cursor[N_NODES];
__device__ __align__(8) int2 g_pair[N_EDGES];  // (src node id, original edge id), grouped by dst

__device__ __forceinline__ float4 h4_to_f4(uint2 u) {
    __half2 h0 = *reinterpret_cast<__half2*>(&u.x);
    __half2 h1 = *reinterpret_cast<__half2*>(&u.y);
    float2 a = __half22float2(h0), b = __half22float2(h1);
    return make_float4(a.x, a.y, b.x, b.y);
}
__device__ __forceinline__ uint2 f4_to_h4(float4 f) {
    __half2 h0 = __floats2half2_rn(f.x, f.y);
    __half2 h1 = __floats2half2_rn(f.z, f.w);
    uint2 u;
    u.x = *reinterpret_cast<uint32_t*>(&h0);
    u.y = *reinterpret_cast<uint32_t*>(&h1);
    return u;
}

__global__ void k_zero_cnt() {
    int i = blockIdx.x * blockDim.x + threadIdx.x;
    if (i < N_NODES) g_cnt[i] = 0;
}

__global__ void k_hist(const int* __restrict__ dst) {
    int e = blockIdx.x * blockDim.x + threadIdx.x;
    if (e < N_EDGES) atomicAdd(&g_cnt[dst[e]], 1);
}

// Single-block exclusive scan over 10000 counts -> rowptr, cursor, invdeg.
__global__ void k_scan() {
    __shared__ int warp_sums[32];
    const int CH = 10;
    int tid = threadIdx.x;
    int base = tid * CH;
    int local[CH];
    int s = 0;
#pragma unroll
    for (int i = 0; i < CH; i++) {
        int idx = base + i;
        int v = (idx < N_NODES) ? g_cnt[idx] : 0;
        local[i] = s;
        s += v;
    }
    int lane = tid & 31, wid = tid >> 5;
    int x = s;
#pragma unroll
    for (int off = 1; off < 32; off <<= 1) {
        int y = __shfl_up_sync(0xffffffffu, x, off);
        if (lane >= off) x += y;
    }
    if (lane == 31) warp_sums[wid] = x;
    __syncthreads();
    if (wid == 0) {
        int y = warp_sums[lane];
#pragma unroll
        for (int off = 1; off < 32; off <<= 1) {
            int z = __shfl_up_sync(0xffffffffu, y, off);
            if (lane >= off) y += z;
        }
        warp_sums[lane] = y;
    }
    __syncthreads();
    int thread_excl = x - s + ((wid > 0) ? warp_sums[wid - 1] : 0);
#pragma unroll
    for (int i = 0; i < CH; i++) {
        int idx = base + i;
        if (idx < N_NODES) {
            int rp = thread_excl + local[i];
            g_rowptr[idx] = rp;
            g_cursor[idx] = rp;
            g_invdeg[idx] = 1.0f / (float)g_cnt[idx];
        }
    }
}

__global__ void k_fill(const int* __restrict__ src, const int* __restrict__ dst) {
    int e = blockIdx.x * blockDim.x + threadIdx.x;
    if (e >= N_EDGES) return;
    int d = dst[e];
    int pos = atomicAdd(&g_cursor[d], 1);
    g_pair[pos] = make_int2(src[e], e);
}

// Layer-1 aggregation: N1[d] = invdeg[d] * sum_{in-edges} ef[e].  Warp per node.
__global__ void k_aggr_feats(const float* __restrict__ ef) {
    int node = blockIdx.x * (blockDim.x >> 5) + (threadIdx.x >> 5);
    if (node >= N_NODES) return;
    int lane = threadIdx.x & 31;
    int rp = g_rowptr[node], deg = g_cnt[node];
    float4 a0 = make_float4(0.f, 0.f, 0.f, 0.f);
    float4 a1 = make_float4(0.f, 0.f, 0.f, 0.f);
    for (int base = 0; base < deg; base += 32) {
        int rem = deg - base;
        int cnt = rem < 32 ? rem : 32;
        int eid = (lane < cnt) ? g_pair[rp + base + lane].y : 0;
        int j = 0;
        for (; j + 4 <= cnt; j += 4) {
            int e0 = __shfl_sync(0xffffffffu, eid, j + 0);
            int e1 = __shfl_sync(0xffffffffu, eid, j + 1);
            int e2 = __shfl_sync(0xffffffffu, eid, j + 2);
            int e3 = __shfl_sync(0xffffffffu, eid, j + 3);
            float4 v0 = reinterpret_cast<const float4*>(ef + (size_t)e0 * F)[lane];
            float4 v1 = reinterpret_cast<const float4*>(ef + (size_t)e1 * F)[lane];
            float4 v2 = reinterpret_cast<const float4*>(ef + (size_t)e2 * F)[lane];
            float4 v3 = reinterpret_cast<const float4*>(ef + (size_t)e3 * F)[lane];
            a0.x += v0.x + v1.x; a0.y += v0.y + v1.y; a0.z += v0.z + v1.z; a0.w += v0.w + v1.w;
            a1.x += v2.x + v3.x; a1.y += v2.y + v3.y; a1.z += v2.z + v3.z; a1.w += v2.w + v3.w;
        }
        for (; j < cnt; j++) {
            int e = __shfl_sync(0xffffffffu, eid, j);
            float4 v = reinterpret_cast<const float4*>(ef + (size_t)e * F)[lane];
            a0.x += v.x; a0.y += v.y; a0.z += v.z; a0.w += v.w;
        }
    }
    float inv = g_invdeg[node];
    float4 acc;
    acc.x = (a0.x + a1.x) * inv; acc.y = (a0.y + a1.y) * inv;
    acc.z = (a0.z + a1.z) * inv; acc.w = (a0.w + a1.w) * inv;
    reinterpret_cast<uint2*>(g_N1h + (size_t)node * F)[lane] = f4_to_h4(acc);
}

// Send/recv: N2[d] = sum_{in-edges} N1[src] (fp16 gather, fp32 accumulate).
__global__ void k_sendrecv() {
    int node = blockIdx.x * (blockDim.x >> 5) + (threadIdx.x >> 5);
    if (node >= N_NODES) return;
    int lane = threadIdx.x & 31;
    int rp = g_rowptr[node], deg = g_cnt[node];
    float4 a0 = make_float4(0.f, 0.f, 0.f, 0.f);
    float4 a1 = make_float4(0.f, 0.f, 0.f, 0.f);
    for (int base = 0; base < deg; base += 32) {
        int rem = deg - base;
        int cnt = rem < 32 ? rem : 32;
        int sreg = (lane < cnt) ? g_pair[rp + base + lane].x : 0;
        int j = 0;
        for (; j + 4 <= cnt; j += 4) {
            int s0 = __shfl_sync(0xffffffffu, sreg, j + 0);
            int s1 = __shfl_sync(0xffffffffu, sreg, j + 1);
            int s2 = __shfl_sync(0xffffffffu, sreg, j + 2);
            int s3 = __shfl_sync(0xffffffffu, sreg, j + 3);
            float4 v0 = h4_to_f4(reinterpret_cast<const uint2*>(g_N1h + (size_t)s0 * F)[lane]);
            float4 v1 = h4_to_f4(reinterpret_cast<const uint2*>(g_N1h + (size_t)s1 * F)[lane]);
            float4 v2 = h4_to_f4(reinterpret_cast<const uint2*>(g_N1h + (size_t)s2 * F)[lane]);
            float4 v3 = h4_to_f4(reinterpret_cast<const uint2*>(g_N1h + (size_t)s3 * F)[lane]);
            a0.x += v0.x + v1.x; a0.y += v0.y + v1.y; a0.z += v0.z + v1.z; a0.w += v0.w + v1.w;
            a1.x += v2.x + v3.x; a1.y += v2.y + v3.y; a1.z += v2.z + v3.z; a1.w += v2.w + v3.w;
        }
        for (; j < cnt; j++) {
            int s = __shfl_sync(0xffffffffu, sreg, j);
            float4 v = h4_to_f4(reinterpret_cast<const uint2*>(g_N1h + (size_t)s * F)[lane]);
            a0.x += v.x; a0.y += v.y; a0.z += v.z; a0.w += v.w;
        }
    }
    float4 acc;
    acc.x = a0.x + a1.x; acc.y = a0.y + a1.y; acc.z = a0.z + a1.z; acc.w = a0.w + a1.w;
    reinterpret_cast<float4*>(g_N2 + (size_t)node * F)[lane] = acc;
}

// Node GEMM: Y[n][j] = dot(N2[n], W[j]).  HALF_OUT selects fp16 vs fp32 output table.
template<int FOUT, bool HALF_OUT>
__global__ void k_gemm(const float* __restrict__ W) {
    __shared__ __align__(16) float As[16 * F];
    int tid = threadIdx.x;
    int r0 = blockIdx.x * 16;

    const float4* A4 = reinterpret_cast<const float4*>(g_N2 + (size_t)r0 * F);
    float4* S4 = reinterpret_cast<float4*>(As);
    for (int i = tid; i < 16 * F / 4; i += FOUT) S4[i] = A4[i];
    __syncthreads();

    float acc[16];
#pragma unroll
    for (int r = 0; r < 16; r++) acc[r] = 0.0f;

    const float4* W4 = reinterpret_cast<const float4*>(W + (size_t)tid * F);
#pragma unroll 4
    for (int k4 = 0; k4 < F / 4; k4++) {
        float4 w = W4[k4];
#pragma unroll
        for (int r = 0; r < 16; r++) {
            float4 a = reinterpret_cast<const float4*>(As + r * F)[k4];
            acc[r] += a.x * w.x + a.y * w.y + a.z * w.z + a.w * w.w;
        }
    }
#pragma unroll
    for (int r = 0; r < 16; r++) {
        if (HALF_OUT)
            g_Yh[(size_t)(r0 + r) * FOUT + tid] = __float2half_rn(acc[r]);
        else
            g_Yf[(size_t)(r0 + r) * FOUT + tid] = acc[r];
    }
}

// Edge update fused with next layer's aggregation (fp16 Y gather):
// N1[d] = invdeg[d] * sum_{in-edges e} relu(Y[src_e]*0.5 + (Y[d]*0.5 + b)).
__global__ void k_edge_update(const float* __restrict__ b) {
    int node = blockIdx.x * (blockDim.x >> 5) + (threadIdx.x >> 5);
    if (node >= N_NODES) return;
    int lane = threadIdx.x & 31;
    int rp = g_rowptr[node], deg = g_cnt[node];
    float4 yd = h4_to_f4(reinterpret_cast<const uint2*>(g_Yh + (size_t)node * F)[lane]);
    float4 bb = reinterpret_cast<const float4*>(b)[lane];
    float4 c;
    c.x = yd.x * 0.5f + bb.x; c.y = yd.y * 0.5f + bb.y;
    c.z = yd.z * 0.5f + bb.z; c.w = yd.w * 0.5f + bb.w;
    float4 a0 = make_float4(0.f, 0.f, 0.f, 0.f);
    float4 a1 = make_float4(0.f, 0.f, 0.f, 0.f);
    for (int base = 0; base < deg; base += 32) {
        int rem = deg - base;
        int cnt = rem < 32 ? rem : 32;
        int sreg = (lane < cnt) ? g_pair[rp + base + lane].x : 0;
        int j = 0;
        for (; j + 4 <= cnt; j += 4) {
            int s0 = __shfl_sync(0xffffffffu, sreg, j + 0);
            int s1 = __shfl_sync(0xffffffffu, sreg, j + 1);
            int s2 = __shfl_sync(0xffffffffu, sreg, j + 2);
            int s3 = __shfl_sync(0xffffffffu, sreg, j + 3);
            float4 v0 = h4_to_f4(reinterpret_cast<const uint2*>(g_Yh + (size_t)s0 * F)[lane]);
            float4 v1 = h4_to_f4(reinterpret_cast<const uint2*>(g_Yh + (size_t)s1 * F)[lane]);
            float4 v2 = h4_to_f4(reinterpret_cast<const uint2*>(g_Yh + (size_t)s2 * F)[lane]);
            float4 v3 = h4_to_f4(reinterpret_cast<const uint2*>(g_Yh + (size_t)s3 * F)[lane]);
            a0.x += fmaxf(0.0f, v0.x * 0.5f + c.x) + fmaxf(0.0f, v1.x * 0.5f + c.x);
            a0.y += fmaxf(0.0f, v0.y * 0.5f + c.y) + fmaxf(0.0f, v1.y * 0.5f + c.y);
            a0.z += fmaxf(0.0f, v0.z * 0.5f + c.z) + fmaxf(0.0f, v1.z * 0.5f + c.z);
            a0.w += fmaxf(0.0f, v0.w * 0.5f + c.w) + fmaxf(0.0f, v1.w * 0.5f + c.w);
            a1.x += fmaxf(0.0f, v2.x * 0.5f + c.x) + fmaxf(0.0f, v3.x * 0.5f + c.x);
            a1.y += fmaxf(0.0f, v2.y * 0.5f + c.y) + fmaxf(0.0f, v3.y * 0.5f + c.y);
            a1.z += fmaxf(0.0f, v2.z * 0.5f + c.z) + fmaxf(0.0f, v3.z * 0.5f + c.z);
            a1.w += fmaxf(0.0f, v2.w * 0.5f + c.w) + fmaxf(0.0f, v3.w * 0.5f + c.w);
        }
        for (; j < cnt; j++) {
            int s = __shfl_sync(0xffffffffu, sreg, j);
            float4 v = h4_to_f4(reinterpret_cast<const uint2*>(g_Yh + (size_t)s * F)[lane]);
            a0.x += fmaxf(0.0f, v.x * 0.5f + c.x);
            a0.y += fmaxf(0.0f, v.y * 0.5f + c.y);
            a0.z += fmaxf(0.0f, v.z * 0.5f + c.z);
            a0.w += fmaxf(0.0f, v.w * 0.5f + c.w);
        }
    }
    float inv = g_invdeg[node];
    float4 acc;
    acc.x = (a0.x + a1.x) * inv; acc.y = (a0.y + a1.y) * inv;
    acc.z = (a0.z + a1.z) * inv; acc.w = (a0.w + a1.w) * inv;
    reinterpret_cast<uint2*>(g_N1h + (size_t)node * F)[lane] = f4_to_h4(acc);
}

// Final layer (FOUT=64, no relu), CSR order, fp32 Y: warp per node.
__global__ void k_final_csr(const float* __restrict__ b, float* __restrict__ out) {
    int node = blockIdx.x * (blockDim.x >> 5) + (threadIdx.x >> 5);
    if (node >= N_NODES) return;
    int lane = threadIdx.x & 31;
    int rp = g_rowptr[node], deg = g_cnt[node];
    float2 yd = reinterpret_cast<const float2*>(g_Yf + (size_t)node * NCLS)[lane];
    float2 bb = reinterpret_cast<const float2*>(b)[lane];
    float2 c;
    c.x = yd.x * 0.5f + bb.x;
    c.y = yd.y * 0.5f + bb.y;
    for (int base = 0; base < deg; base += 32) {
        int rem = deg - base;
        int cnt = rem < 32 ? rem : 32;
        int2 pr = (lane < cnt) ? g_pair[rp + base + lane] : make_int2(0, 0);
        int j = 0;
        for (; j + 2 <= cnt; j += 2) {
            int s0 = __shfl_sync(0xffffffffu, pr.x, j + 0);
            int e0 = __shfl_sync(0xffffffffu, pr.y, j + 0);
            int s1 = __shfl_sync(0xffffffffu, pr.x, j + 1);
            int e1 = __shfl_sync(0xffffffffu, pr.y, j + 1);
            float2 v0 = reinterpret_cast<const float2*>(g_Yf + (size_t)s0 * NCLS)[lane];
            float2 v1 = reinterpret_cast<const float2*>(g_Yf + (size_t)s1 * NCLS)[lane];
            float2 o0, o1;
            o0.x = v0.x * 0.5f + c.x; o0.y = v0.y * 0.5f + c.y;
            o1.x = v1.x * 0.5f + c.x; o1.y = v1.y * 0.5f + c.y;
            reinterpret_cast<float2*>(out)[(size_t)e0 * (NCLS / 2) + lane] = o0;
            reinterpret_cast<float2*>(out)[(size_t)e1 * (NCLS / 2) + lane] = o1;
        }
        for (; j < cnt; j++) {
            int s = __shfl_sync(0xffffffffu, pr.x, j);
            int e = __shfl_sync(0xffffffffu, pr.y, j);
            float2 v = reinterpret_cast<const float2*>(g_Yf + (size_t)s * NCLS)[lane];
            float2 o;
            o.x = v.x * 0.5f + c.x; o.y = v.y * 0.5f + c.y;
            reinterpret_cast<float2*>(out)[(size_t)e * (NCLS / 2) + lane] = o;
        }
    }
}

extern "C" void kernel_launch(void* const* d_in, const int* in_sizes, int n_in,
                              void* d_out, int out_size) {
    const float* ef  = (const float*)d_in[0];
    const int*   src = (const int*)d_in[1];
    const int*   dst = (const int*)d_in[2];
    const float* W1 = (const float*)d_in[3];  const float* b1 = (const float*)d_in[4];
    const float* W2 = (const float*)d_in[5];  const float* b2 = (const float*)d_in[6];
    const float* W3 = (const float*)d_in[7];  const float* b3 = (const float*)d_in[8];
    const float* W4 = (const float*)d_in[9];  const float* b4 = (const float*)d_in[10];
    const float* W5 = (const float*)d_in[11]; const float* b5 = (const float*)d_in[12];
    float* out = (float*)d_out;

    const int NB = (N_NODES + 7) / 8;   // warp-per-node blocks (256 thr = 8 warps)

    // CSR build (counting sort by dst)
    k_zero_cnt<<<(N_NODES + 255) / 256, 256>>>();
    k_hist<<<N_EDGES / 256, 256>>>(dst);
    k_scan<<<1, 1024>>>();
    k_fill<<<N_EDGES / 256, 256>>>(src, dst);

    // layer-1 input aggregation
    k_aggr_feats<<<NB, 256>>>(ef);

    const float* Ws[4] = {W1, W2, W3, W4};
    const float* bs[4] = {b1, b2, b3, b4};
    for (int l = 0; l < 4; l++) {
        k_sendrecv<<<NB, 256>>>();                          // N2[d] = sum N1h[src]
        k_gemm<F, true><<<N_NODES / 16, F>>>(Ws[l]);        // Yh = N2 @ W^T (fp16 out)
        k_edge_update<<<NB, 256>>>(bs[l]);                  // N1h = invdeg*sum relu(...)
    }

    // final layer (fp32 Y to protect output precision)
    k_sendrecv<<<NB, 256>>>();
    k_gemm<NCLS, false><<<N_NODES / 16, NCLS>>>(W5);
    k_final_csr<<<NB, 256>>>(b5, out);
}